// round 3
// baseline (speedup 1.0000x reference)
#include <cuda_runtime.h>
#include <math.h>

// Problem constants
#define BATCH 2
#define CC    128
#define HW    4096           // H*W
#define NPIX  8192           // B*H*W
#define NCLS  4
#define KSEL  50
#define KPAD  64
#define NBIN  1024
#define MAXCAND 2048
// exp(x/tau) = exp2f(x * log2(e)/0.07)
#define SCALE 20.6099291555566197f

typedef unsigned long long u64;

// ---------------- f32x2 helpers (sm_103a packed fp32 FMA) ----------------
__device__ __forceinline__ void fma2(u64& acc, u64 a, u64 b) {
    asm("fma.rn.f32x2 %0, %1, %2, %0;" : "+l"(acc) : "l"(a), "l"(b));
}
__device__ __forceinline__ float2 upk(u64 v) {
    float2 r; asm("mov.b64 {%0,%1}, %2;" : "=f"(r.x), "=f"(r.y) : "l"(v)); return r;
}

// ---------------- device scratch (no allocations allowed) ----------------
__device__ float4 g_inT4[NPIX * 32];      // normalized input,   [N][128] as float4[N][32]
__device__ float4 g_posT4[NPIX * 32];     // normalized positive
__device__ float  g_pos_sim[NPIX];
__device__ int    g_seg_in[NPIX];
__device__ int    g_seg_neg[NPIX];
__device__ float  g_neg_prob[NPIX];
__device__ float  g_Gs[NCLS][KPAD][CC];   // selected negatives, normalized AND pre-scaled by SCALE
__device__ float  g_acc;

// ---------------- kernel 1: seg / prob from 4-class logits (+zero acc) ----------------
__global__ void k_seg(const float* __restrict__ il, const float* __restrict__ nl) {
    int n = blockIdx.x * 256 + threadIdx.x;
    if (n == 0) g_acc = 0.0f;
    if (n >= NPIX) return;
    int b = n >> 12, rem = n & 4095;

    const float* pi = il + (size_t)b * NCLS * HW + rem;
    float l0 = pi[0], l1 = pi[HW], l2 = pi[2 * HW], l3 = pi[3 * HW];
    int amax = 0; float m = l0;
    if (l1 > m) { m = l1; amax = 1; }
    if (l2 > m) { m = l2; amax = 2; }
    if (l3 > m) { m = l3; amax = 3; }
    g_seg_in[n] = amax;

    const float* pn = nl + (size_t)b * NCLS * HW + rem;
    l0 = pn[0]; l1 = pn[HW]; l2 = pn[2 * HW]; l3 = pn[3 * HW];
    amax = 0; m = l0;
    if (l1 > m) { m = l1; amax = 1; }
    if (l2 > m) { m = l2; amax = 2; }
    if (l3 > m) { m = l3; amax = 3; }
    float s = __expf(l0 - m) + __expf(l1 - m) + __expf(l2 - m) + __expf(l3 - m);
    g_seg_neg[n]  = amax;
    g_neg_prob[n] = 1.0f / s;   // max softmax prob
}

// ---------------- kernel 2: normalize+transpose input/positive, pos_sim ----------------
__global__ void k_norm(const float* __restrict__ inp, const float* __restrict__ pos) {
    __shared__ float s_in[CC * 33];
    __shared__ float s_po[CC * 33];
    __shared__ float s_red[3 * 8 * 32];
    __shared__ float s_invi[32], s_invp[32];

    int t = threadIdx.x;
    int base = blockIdx.x * 32;
    int b = base >> 12, rem0 = base & 4095;

    #pragma unroll
    for (int i = 0; i < 16; i++) {
        int idx = i * 256 + t;
        int c = idx >> 5, p = idx & 31;
        size_t g = (size_t)(b * CC + c) * HW + rem0 + p;
        s_in[c * 33 + p] = inp[g];
        s_po[c * 33 + p] = pos[g];
    }
    __syncthreads();

    {
        int g = t >> 5, p = t & 31;
        float ssi = 0.f, ssp = 0.f, dp = 0.f;
        #pragma unroll
        for (int j = 0; j < 16; j++) {
            int c = g * 16 + j;
            float a = s_in[c * 33 + p];
            float q = s_po[c * 33 + p];
            ssi += a * a; ssp += q * q; dp += a * q;
        }
        s_red[(0 * 8 + g) * 32 + p] = ssi;
        s_red[(1 * 8 + g) * 32 + p] = ssp;
        s_red[(2 * 8 + g) * 32 + p] = dp;
    }
    __syncthreads();

    if (t < 32) {
        int p = t;
        float ssi = 0.f, ssp = 0.f, dp = 0.f;
        #pragma unroll
        for (int g = 0; g < 8; g++) {
            ssi += s_red[(0 * 8 + g) * 32 + p];
            ssp += s_red[(1 * 8 + g) * 32 + p];
            dp  += s_red[(2 * 8 + g) * 32 + p];
        }
        float invi = 1.0f / fmaxf(sqrtf(ssi), 1e-12f);
        float invp = 1.0f / fmaxf(sqrtf(ssp), 1e-12f);
        s_invi[p] = invi;
        s_invp[p] = invp;
        g_pos_sim[base + p] = dp * invi * invp;
    }
    __syncthreads();

    {
        int w = t >> 5, lane = t & 31;
        float* oi = (float*)g_inT4;
        float* op = (float*)g_posT4;
        #pragma unroll
        for (int j = 0; j < 4; j++) {
            int p = w * 4 + j;
            float invi = s_invi[p], invp = s_invp[p];
            size_t row = (size_t)(base + p) * CC;
            #pragma unroll
            for (int ch = 0; ch < 4; ch++) {
                int c = ch * 32 + lane;
                oi[row + c] = s_in[c * 33 + p] * invi;
                op[row + c] = s_po[c * 33 + p] * invp;
            }
        }
    }
}

// ---------------- kernel 3: per-class top-50 selection + gather (fused) ----------------
__global__ __launch_bounds__(1024, 1) void k_select(const float* __restrict__ neg) {
    __shared__ int   hist[NBIN];
    __shared__ int   s_chunk[32];
    __shared__ float cv[MAXCAND];
    __shared__ int   ci[MAXCAND];
    __shared__ int   s_sel[KSEL];
    __shared__ int   s_cnt;
    __shared__ int   s_binThr;

    int s = blockIdx.x;
    int t = threadIdx.x;

    // zero k-pad rows of G (rows 50..63 of this class)
    for (int i = t; i < (KPAD - KSEL) * CC; i += 1024)
        (&g_Gs[s][KSEL][0])[i] = 0.0f;

    // ---- register prefetch: 8 elements per thread ----
    int  seg[8];
    float pv[8];
    int  bin[8];
    {
        const int4*   ps = (const int4*)(g_seg_neg) + t * 2;
        const float4* pp = (const float4*)(g_neg_prob) + t * 2;
        int4 s0 = ps[0], s1 = ps[1];
        float4 p0 = pp[0], p1 = pp[1];
        seg[0]=s0.x; seg[1]=s0.y; seg[2]=s0.z; seg[3]=s0.w;
        seg[4]=s1.x; seg[5]=s1.y; seg[6]=s1.z; seg[7]=s1.w;
        pv[0]=p0.x; pv[1]=p0.y; pv[2]=p0.z; pv[3]=p0.w;
        pv[4]=p1.x; pv[5]=p1.y; pv[6]=p1.z; pv[7]=p1.w;
        #pragma unroll
        for (int j = 0; j < 8; j++) {
            int b = (int)((pv[j] - 0.25f) * (1024.0f / 0.75f));
            bin[j] = max(0, min(NBIN - 1, b));
        }
    }

    for (int i = t; i < NBIN; i += 1024) hist[i] = 0;
    if (t == 0) s_cnt = 0;
    __syncthreads();

    #pragma unroll
    for (int j = 0; j < 8; j++)
        if (seg[j] != s) atomicAdd(&hist[bin[j]], 1);
    __syncthreads();

    if (t < 32) {
        int sum = 0;
        #pragma unroll
        for (int j = 0; j < 32; j++) sum += hist[t * 32 + j];
        s_chunk[t] = sum;
    }
    __syncthreads();
    if (t == 0) {
        int cum = 0, binThr = 0;
        for (int cb = 31; cb >= 0; cb--) {
            if (cum + s_chunk[cb] >= KSEL) {
                for (int bb = cb * 32 + 31; bb >= cb * 32; bb--) {
                    cum += hist[bb];
                    if (cum >= KSEL) { binThr = bb; break; }
                }
                break;
            }
            cum += s_chunk[cb];
        }
        s_binThr = binThr;
    }
    __syncthreads();
    int binThr = s_binThr;

    #pragma unroll
    for (int j = 0; j < 8; j++) {
        if (seg[j] != s && bin[j] >= binThr) {
            int pos = atomicAdd(&s_cnt, 1);
            if (pos < MAXCAND) { cv[pos] = pv[j]; ci[pos] = t * 8 + j; }
        }
    }
    __syncthreads();
    int M = min(s_cnt, MAXCAND);

    // exact rank (value desc, index asc tie-break == lax.top_k)
    for (int c = t; c < M; c += 1024) {
        float v = cv[c]; int id = ci[c];
        int r = 0;
        for (int m = 0; m < M; m++) {
            float vm = cv[m];
            if (vm > v || (vm == v && ci[m] < id)) r++;
        }
        if (r < KSEL) s_sel[r] = id;
    }
    __syncthreads();

    // gather + normalize + pre-scale the 50 selected negatives
    {
        int w = t >> 5, lane = t & 31;
        for (int k = w; k < KSEL; k += 32) {
            int n = s_sel[k];
            int b = n >> 12, rem = n & 4095;
            const float* p = neg + (size_t)b * CC * HW + rem;
            float v[4]; float ss = 0.f;
            #pragma unroll
            for (int j = 0; j < 4; j++) {
                int c = lane + j * 32;
                v[j] = p[(size_t)c * HW];
                ss += v[j] * v[j];
            }
            #pragma unroll
            for (int off = 16; off; off >>= 1) ss += __shfl_xor_sync(0xffffffffu, ss, off);
            float inv = SCALE / fmaxf(sqrtf(ss), 1e-12f);
            #pragma unroll
            for (int j = 0; j < 4; j++) {
                int c = lane + j * 32;
                g_Gs[s][k][c] = v[j] * inv;
            }
        }
    }
}

// ---------------- kernel 4: main contrastive accumulation (lanes-over-k) ----------------
// warp handles 4 pixels; lane l owns negatives k=2l, 2l+1 (lanes 0..24 valid).
__global__ __launch_bounds__(256, 3) void k_main2() {
    __shared__ float4 sx[8][4][32];   // [warp][px][c4]
    __shared__ float4 sp[8][4][32];
    __shared__ float  s_part[8];

    int warp = threadIdx.x >> 5, lane = threadIdx.x & 31;
    int px0 = (blockIdx.x * 8 + warp) * 4;
    int k0 = lane * 2;

    // stage x/p rows for this warp's 4 pixels (coalesced)
    #pragma unroll
    for (int r = 0; r < 4; r++) {
        int idx = r * 32 + lane;          // 0..127
        int u = idx >> 5, c4 = idx & 31;
        sx[warp][u][c4] = g_inT4[(size_t)(px0 + u) * 32 + c4];
        sp[warp][u][c4] = g_posT4[(size_t)(px0 + u) * 32 + c4];
    }
    __syncwarp();

    // per-pixel class -> G row pointers (rows k0 and k0+1)
    const ulonglong2* gp[4];
    #pragma unroll
    for (int u = 0; u < 4; u++) {
        int cls = g_seg_in[px0 + u];
        gp[u] = (const ulonglong2*)(&g_Gs[cls][k0][0]);
    }

    u64 aN[4][2], aA[4][2];
    #pragma unroll
    for (int u = 0; u < 4; u++) { aN[u][0]=0; aN[u][1]=0; aA[u][0]=0; aA[u][1]=0; }

    const ulonglong2* sxw = (const ulonglong2*)&sx[warp][0][0];
    const ulonglong2* spw = (const ulonglong2*)&sp[warp][0][0];

    #pragma unroll 4
    for (int c4 = 0; c4 < 32; c4++) {
        #pragma unroll
        for (int u = 0; u < 4; u++) {
            ulonglong2 x2 = sxw[u * 32 + c4];
            ulonglong2 p2 = spw[u * 32 + c4];
            ulonglong2 g0 = __ldg(gp[u] + c4);            // row k0
            ulonglong2 g1 = __ldg(gp[u] + (CC/4) + c4);   // row k0+1
            fma2(aN[u][0], x2.x, g0.x); fma2(aN[u][0], x2.y, g0.y);
            fma2(aN[u][1], x2.x, g1.x); fma2(aN[u][1], x2.y, g1.y);
            fma2(aA[u][0], p2.x, g0.x); fma2(aA[u][0], p2.y, g0.y);
            fma2(aA[u][1], p2.x, g1.x); fma2(aA[u][1], p2.y, g1.y);
        }
    }

    // epilogue: per-pixel exp-sums, one warp reduction per pixel
    bool kv = (k0 < KSEL);
    float sumN[4], sumA[4];
    #pragma unroll
    for (int u = 0; u < 4; u++) {
        float2 n0 = upk(aN[u][0]), n1 = upk(aN[u][1]);
        float2 a0 = upk(aA[u][0]), a1 = upk(aA[u][1]);
        float en = kv ? (exp2f(n0.x + n0.y) + exp2f(n1.x + n1.y)) : 0.f;
        float ea = kv ? (exp2f(a0.x + a0.y) + exp2f(a1.x + a1.y)) : 0.f;
        #pragma unroll
        for (int off = 16; off; off >>= 1) {
            en += __shfl_xor_sync(0xffffffffu, en, off);
            ea += __shfl_xor_sync(0xffffffffu, ea, off);
        }
        sumN[u] = en; sumA[u] = ea;
    }

    if (lane == 0) {
        float t = 0.f;
        #pragma unroll
        for (int u = 0; u < 4; u++) {
            float ps  = g_pos_sim[px0 + u];
            float nom = exp2f(ps * SCALE);
            t += __logf(nom / (sumN[u] + nom + 1e-8f))
               + __logf(nom / (sumA[u] + nom + 1e-8f));
        }
        s_part[warp] = t;
    }
    __syncthreads();
    if (threadIdx.x == 0) {
        float s = 0.f;
        #pragma unroll
        for (int i = 0; i < 8; i++) s += s_part[i];
        atomicAdd(&g_acc, s);
    }
}

// ---------------- kernel 5: finalize ----------------
__global__ void k_final(float* __restrict__ out) {
    out[0] = -g_acc / (float)NPIX;
}

// ---------------- launch ----------------
extern "C" void kernel_launch(void* const* d_in, const int* in_sizes, int n_in,
                              void* d_out, int out_size) {
    const float* inp = (const float*)d_in[0];   // input    [2,128,64,64]
    const float* pos = (const float*)d_in[1];   // positive
    const float* neg = (const float*)d_in[2];   // negative
    const float* il  = (const float*)d_in[3];   // input_logits    [2,4,64,64]
    const float* nl  = (const float*)d_in[4];   // negative_logits
    float* out = (float*)d_out;

    k_seg<<<NPIX / 256, 256>>>(il, nl);
    k_norm<<<NPIX / 32, 256>>>(inp, pos);
    k_select<<<NCLS, 1024>>>(neg);
    k_main2<<<NPIX / 32, 256>>>();
    k_final<<<1, 1>>>(out);
}

// round 4
// speedup vs baseline: 2.8130x; 2.8130x over previous
#include <cuda_runtime.h>
#include <math.h>

// Problem constants
#define BATCH 2
#define CC    128
#define HW    4096           // H*W
#define NPIX  8192           // B*H*W
#define NCLS  4
#define KSEL  50
#define KPAD  64
#define NBIN  1024
#define MAXCAND 2048
// exp(x/tau) = exp2f(x * log2(e)/0.07)
#define SCALE 20.6099291555566197f

#define RS 132                       // padded row stride (floats) for X/P tiles
#define CS (KPAD * CC + 4)           // class stride (floats) in sG: 8196

// smem layout (floats)
#define OFF_X   0
#define OFF_P   (OFF_X + 64 * RS)            // 8448
#define OFF_G   (OFF_P + 64 * RS)            // 16896
#define OFF_RED (OFF_G + NCLS * CS)          // 49680
#define OFF_EX  (OFF_RED + 3 * 8 * 64)       // 51216
#define OFF_INV (OFF_EX + 2 * 8 * 64)        // 52240
#define OFF_NOM (OFF_INV + 64)               // 52304
#define OFF_CLS (OFF_NOM + 64)               // 52368
#define SMEM_FLOATS (OFF_CLS + 64)           // 52432
#define SMEM_BYTES  (SMEM_FLOATS * 4)        // 209728

typedef unsigned long long u64;

__device__ __forceinline__ void fma2(u64& acc, u64 a, u64 b) {
    asm("fma.rn.f32x2 %0, %1, %2, %0;" : "+l"(acc) : "l"(a), "l"(b));
}
__device__ __forceinline__ float2 upk(u64 v) {
    float2 r; asm("mov.b64 {%0,%1}, %2;" : "=f"(r.x), "=f"(r.y) : "l"(v)); return r;
}

// ---------------- device scratch ----------------
__device__ int    g_seg_in[NPIX];
__device__ int    g_seg_neg[NPIX];
__device__ float  g_neg_prob[NPIX];
__device__ float  g_Gs[NCLS][KPAD][CC];   // selected negatives, normalized AND pre-scaled by SCALE
__device__ float  g_acc;

// ---------------- kernel 1: seg / prob from 4-class logits (+zero acc) ----------------
__global__ void k_seg(const float* __restrict__ il, const float* __restrict__ nl) {
    int n = blockIdx.x * 256 + threadIdx.x;
    if (n == 0) g_acc = 0.0f;
    if (n >= NPIX) return;
    int b = n >> 12, rem = n & 4095;

    const float* pi = il + (size_t)b * NCLS * HW + rem;
    float l0 = pi[0], l1 = pi[HW], l2 = pi[2 * HW], l3 = pi[3 * HW];
    int amax = 0; float m = l0;
    if (l1 > m) { m = l1; amax = 1; }
    if (l2 > m) { m = l2; amax = 2; }
    if (l3 > m) { m = l3; amax = 3; }
    g_seg_in[n] = amax;

    const float* pn = nl + (size_t)b * NCLS * HW + rem;
    l0 = pn[0]; l1 = pn[HW]; l2 = pn[2 * HW]; l3 = pn[3 * HW];
    amax = 0; m = l0;
    if (l1 > m) { m = l1; amax = 1; }
    if (l2 > m) { m = l2; amax = 2; }
    if (l3 > m) { m = l3; amax = 3; }
    float s = __expf(l0 - m) + __expf(l1 - m) + __expf(l2 - m) + __expf(l3 - m);
    g_seg_neg[n]  = amax;
    g_neg_prob[n] = 1.0f / s;   // max softmax prob
}

// ---------------- kernel 2: per-class top-50 selection + gather (fused) ----------------
__global__ __launch_bounds__(1024, 1) void k_select(const float* __restrict__ neg) {
    __shared__ int   hist[NBIN];
    __shared__ int   s_chunk[32];
    __shared__ float cv[MAXCAND];
    __shared__ int   ci[MAXCAND];
    __shared__ int   s_sel[KSEL];
    __shared__ int   s_cnt;
    __shared__ int   s_binThr;

    int s = blockIdx.x;
    int t = threadIdx.x;

    // zero k-pad rows of G (rows 50..63 of this class)
    for (int i = t; i < (KPAD - KSEL) * CC; i += 1024)
        (&g_Gs[s][KSEL][0])[i] = 0.0f;

    // register prefetch: 8 elements per thread
    int  seg[8];
    float pv[8];
    int  bin[8];
    {
        const int4*   ps = (const int4*)(g_seg_neg) + t * 2;
        const float4* pp = (const float4*)(g_neg_prob) + t * 2;
        int4 s0 = ps[0], s1 = ps[1];
        float4 p0 = pp[0], p1 = pp[1];
        seg[0]=s0.x; seg[1]=s0.y; seg[2]=s0.z; seg[3]=s0.w;
        seg[4]=s1.x; seg[5]=s1.y; seg[6]=s1.z; seg[7]=s1.w;
        pv[0]=p0.x; pv[1]=p0.y; pv[2]=p0.z; pv[3]=p0.w;
        pv[4]=p1.x; pv[5]=p1.y; pv[6]=p1.z; pv[7]=p1.w;
        #pragma unroll
        for (int j = 0; j < 8; j++) {
            int b = (int)((pv[j] - 0.25f) * (1024.0f / 0.75f));
            bin[j] = max(0, min(NBIN - 1, b));
        }
    }

    for (int i = t; i < NBIN; i += 1024) hist[i] = 0;
    if (t == 0) s_cnt = 0;
    __syncthreads();

    #pragma unroll
    for (int j = 0; j < 8; j++)
        if (seg[j] != s) atomicAdd(&hist[bin[j]], 1);
    __syncthreads();

    if (t < 32) {
        int sum = 0;
        #pragma unroll
        for (int j = 0; j < 32; j++) sum += hist[t * 32 + j];
        s_chunk[t] = sum;
    }
    __syncthreads();
    if (t == 0) {
        int cum = 0, binThr = 0;
        for (int cb = 31; cb >= 0; cb--) {
            if (cum + s_chunk[cb] >= KSEL) {
                for (int bb = cb * 32 + 31; bb >= cb * 32; bb--) {
                    cum += hist[bb];
                    if (cum >= KSEL) { binThr = bb; break; }
                }
                break;
            }
            cum += s_chunk[cb];
        }
        s_binThr = binThr;
    }
    __syncthreads();
    int binThr = s_binThr;

    #pragma unroll
    for (int j = 0; j < 8; j++) {
        if (seg[j] != s && bin[j] >= binThr) {
            int pos = atomicAdd(&s_cnt, 1);
            if (pos < MAXCAND) { cv[pos] = pv[j]; ci[pos] = t * 8 + j; }
        }
    }
    __syncthreads();
    int M = min(s_cnt, MAXCAND);

    // exact rank (value desc, index asc tie-break == lax.top_k)
    for (int c = t; c < M; c += 1024) {
        float v = cv[c]; int id = ci[c];
        int r = 0;
        for (int m = 0; m < M; m++) {
            float vm = cv[m];
            if (vm > v || (vm == v && ci[m] < id)) r++;
        }
        if (r < KSEL) s_sel[r] = id;
    }
    __syncthreads();

    // gather + normalize + pre-scale the 50 selected negatives
    {
        int w = t >> 5, lane = t & 31;
        for (int k = w; k < KSEL; k += 32) {
            int n = s_sel[k];
            int b = n >> 12, rem = n & 4095;
            const float* p = neg + (size_t)b * CC * HW + rem;
            float v[4]; float ss = 0.f;
            #pragma unroll
            for (int j = 0; j < 4; j++) {
                int c = lane + j * 32;
                v[j] = p[(size_t)c * HW];
                ss += v[j] * v[j];
            }
            #pragma unroll
            for (int off = 16; off; off >>= 1) ss += __shfl_xor_sync(0xffffffffu, ss, off);
            float inv = SCALE / fmaxf(sqrtf(ss), 1e-12f);
            #pragma unroll
            for (int j = 0; j < 4; j++) {
                int c = lane + j * 32;
                g_Gs[s][k][c] = v[j] * inv;
            }
        }
    }
}

// ---------------- kernel 3: fused norm + block GEMM + contrastive loss ----------------
// 128 blocks x 512 threads; block owns 64 consecutive pixels.
__global__ __launch_bounds__(512, 1) void k_fused(const float* __restrict__ inp,
                                                  const float* __restrict__ pos) {
    extern __shared__ float sm[];
    float* sX   = sm + OFF_X;
    float* sP   = sm + OFF_P;
    float* sG   = sm + OFF_G;
    float* sRed = sm + OFF_RED;
    float* sEx  = sm + OFF_EX;
    float* sInv = sm + OFF_INV;
    float* sNom = sm + OFF_NOM;
    int*   sCls = (int*)(sm + OFF_CLS);

    int tid = threadIdx.x;
    int n   = tid & 63;
    int cg  = tid >> 6;                  // 0..7 (channel group in phase A, k group in phase C)
    int px0 = blockIdx.x * 64;
    int b   = px0 >> 12, rem = px0 & 4095;

    // ---- Phase A: load X/P tiles (coalesced over pixels), partial norms ----
    {
        const float* bx = inp + (size_t)b * CC * HW + rem + n;
        const float* bp = pos + (size_t)b * CC * HW + rem + n;
        float sx2 = 0.f, sp2 = 0.f, sxp = 0.f;
        #pragma unroll
        for (int j4 = 0; j4 < 4; j4++) {
            float xv[4], pv[4];
            #pragma unroll
            for (int e = 0; e < 4; e++) {
                int c = cg * 16 + j4 * 4 + e;
                xv[e] = bx[(size_t)c * HW];
                pv[e] = bp[(size_t)c * HW];
                sx2 += xv[e] * xv[e];
                sp2 += pv[e] * pv[e];
                sxp += xv[e] * pv[e];
            }
            int c0 = cg * 16 + j4 * 4;
            *(float4*)&sX[n * RS + c0] = make_float4(xv[0], xv[1], xv[2], xv[3]);
            *(float4*)&sP[n * RS + c0] = make_float4(pv[0], pv[1], pv[2], pv[3]);
        }
        sRed[(0 * 8 + cg) * 64 + n] = sx2;
        sRed[(1 * 8 + cg) * 64 + n] = sp2;
        sRed[(2 * 8 + cg) * 64 + n] = sxp;
    }
    __syncthreads();

    // ---- Phase B: load all-class G into smem (class-stride padded) ----
    {
        const float4* gsrc = (const float4*)g_Gs;     // 8192 float4
        #pragma unroll
        for (int it = 0; it < 16; it++) {
            int f4 = tid + it * 512;
            int cls = f4 >> 11;                       // 2048 float4 per class
            int r4  = f4 & 2047;
            float4 v = gsrc[f4];
            *(float4*)&sG[cls * CS + r4 * 4] = v;
        }
    }
    // finalize norms / nominator / class (64 threads), overlapped with B's tail
    if (tid < 64) {
        float sx2 = 0.f, sp2 = 0.f, sxp = 0.f;
        #pragma unroll
        for (int g = 0; g < 8; g++) {
            sx2 += sRed[(0 * 8 + g) * 64 + tid];
            sp2 += sRed[(1 * 8 + g) * 64 + tid];
            sxp += sRed[(2 * 8 + g) * 64 + tid];
        }
        float invi = 1.0f / fmaxf(sqrtf(sx2), 1e-12f);
        float invp = 1.0f / fmaxf(sqrtf(sp2), 1e-12f);
        sInv[tid] = invi;
        sNom[tid] = exp2f(sxp * invi * invp * SCALE);
        sCls[tid] = g_seg_in[px0 + tid];
    }
    __syncthreads();

    // ---- Phase C: register-tiled GEMM: thread = (pixel n, 8 negatives kg*8..) ----
    const float* gx = sX + n * RS;
    const float* gp = sP + n * RS;
    int cls = sCls[n];
    const float* gg = sG + cls * CS + cg * 8 * CC;

    u64 aN[8], aA[8];
    #pragma unroll
    for (int kk = 0; kk < 8; kk++) { aN[kk] = 0ull; aA[kk] = 0ull; }

    #pragma unroll 8
    for (int c4 = 0; c4 < 32; c4++) {
        ulonglong2 x2 = *(const ulonglong2*)&gx[c4 * 4];
        ulonglong2 p2 = *(const ulonglong2*)&gp[c4 * 4];
        #pragma unroll
        for (int kk = 0; kk < 8; kk++) {
            ulonglong2 g2 = *(const ulonglong2*)&gg[kk * CC + c4 * 4];
            fma2(aN[kk], x2.x, g2.x); fma2(aN[kk], x2.y, g2.y);
            fma2(aA[kk], p2.x, g2.x); fma2(aA[kk], p2.y, g2.y);
        }
    }

    // ---- epilogue: exp-sums over this thread's 8 k, masked to k<50 ----
    {
        float invi = sInv[n];
        float eN = 0.f, eA = 0.f;
        #pragma unroll
        for (int kk = 0; kk < 8; kk++) {
            int k = cg * 8 + kk;
            if (k < KSEL) {
                float2 tn = upk(aN[kk]);
                float2 ta = upk(aA[kk]);
                eN += exp2f((tn.x + tn.y) * invi);
                eA += exp2f((ta.x + ta.y) * invi);
            }
        }
        sEx[(0 * 8 + cg) * 64 + n] = eN;
        sEx[(1 * 8 + cg) * 64 + n] = eA;
    }
    __syncthreads();

    if (tid < 64) {
        float accN = 0.f, accA = 0.f;
        #pragma unroll
        for (int g = 0; g < 8; g++) {
            accN += sEx[(0 * 8 + g) * 64 + tid];
            accA += sEx[(1 * 8 + g) * 64 + tid];
        }
        float nom = sNom[tid];
        float term = __logf(nom / (accN + nom + 1e-8f))
                   + __logf(nom / (accA + nom + 1e-8f));
        #pragma unroll
        for (int off = 16; off; off >>= 1)
            term += __shfl_xor_sync(0xffffffffu, term, off);
        if ((tid & 31) == 0) atomicAdd(&g_acc, term);
    }
}

// ---------------- kernel 4: finalize ----------------
__global__ void k_final(float* __restrict__ out) {
    out[0] = -g_acc / (float)NPIX;
}

// ---------------- launch ----------------
extern "C" void kernel_launch(void* const* d_in, const int* in_sizes, int n_in,
                              void* d_out, int out_size) {
    const float* inp = (const float*)d_in[0];   // input    [2,128,64,64]
    const float* pos = (const float*)d_in[1];   // positive
    const float* neg = (const float*)d_in[2];   // negative
    const float* il  = (const float*)d_in[3];   // input_logits    [2,4,64,64]
    const float* nl  = (const float*)d_in[4];   // negative_logits
    float* out = (float*)d_out;

    cudaFuncSetAttribute(k_fused, cudaFuncAttributeMaxDynamicSharedMemorySize, SMEM_BYTES);

    k_seg<<<NPIX / 256, 256>>>(il, nl);
    k_select<<<NCLS, 1024>>>(neg);
    k_fused<<<NPIX / 64, 512, SMEM_BYTES>>>(inp, pos);
    k_final<<<1, 1>>>(out);
}

// round 5
// speedup vs baseline: 3.0236x; 1.0749x over previous
#include <cuda_runtime.h>
#include <math.h>

// Problem constants
#define BATCH 2
#define CC    128
#define HW    4096
#define NPIX  8192
#define NCLS  4
#define KSEL  50
#define KPAD  56                       // 4 k-groups x 14
#define NBIN  1024
#define MAXCAND 2048
// exp(x/tau) = exp2f(x * log2(e)/0.07)
#define SCALE 20.6099291555566197f

#define RS 132                         // padded row stride (floats) for X/P tiles
#define CS (KPAD * CC + 4)             // class stride (floats): 7172 (bank offset 4 per class)

// smem layout (floats)
#define OFF_X    0
#define OFF_P    (64 * RS)                   // 8448
#define OFF_G    (2 * 64 * RS)               // 16896
#define OFF_RED  (OFF_G + NCLS * CS)         // 45584
#define OFF_EX   (OFF_RED + 3 * 8 * 64)      // 47120
#define OFF_INV  (OFF_EX + 8 * 64)           // 47632
#define OFF_INVP (OFF_INV + 64)
#define OFF_NOM  (OFF_INVP + 64)
#define OFF_CLS  (OFF_NOM + 64)
#define OFF_PERM (OFF_CLS + 64)
#define OFF_SLOT (OFF_PERM + 64)
#define OFF_CNT  (OFF_SLOT + 64)
#define SMEM_FLOATS (OFF_CNT + 16)
#define SMEM_BYTES  (SMEM_FLOATS * 4)        // ~192 KB

typedef unsigned long long u64;

__device__ __forceinline__ void fma2(u64& acc, u64 a, u64 b) {
    asm("fma.rn.f32x2 %0, %1, %2, %0;" : "+l"(acc) : "l"(a), "l"(b));
}
__device__ __forceinline__ float2 upk(u64 v) {
    float2 r; asm("mov.b64 {%0,%1}, %2;" : "=f"(r.x), "=f"(r.y) : "l"(v)); return r;
}

// ---------------- device scratch ----------------
__device__ float g_Gs[NCLS][KPAD][CC];  // selected negatives, normalized AND pre-scaled by SCALE
__device__ float g_acc;
__device__ unsigned int g_tick;

// ---------------- kernel 1: selection (computes seg/prob from logits inline) ----------------
__global__ __launch_bounds__(1024, 1) void k_select(const float* __restrict__ neg,
                                                    const float* __restrict__ nl) {
    __shared__ int   hist[NBIN];
    __shared__ int   s_chunk[32];
    __shared__ float cv[MAXCAND];
    __shared__ int   ci[MAXCAND];
    __shared__ int   s_sel[KSEL];
    __shared__ int   s_cnt;
    __shared__ int   s_binThr;

    int s = blockIdx.x;
    int t = threadIdx.x;

    if (s == 0 && t == 0) { g_acc = 0.0f; g_tick = 0u; }

    // zero k-pad rows of this class (rows 50..55)
    for (int i = t; i < (KPAD - KSEL) * CC; i += 1024)
        (&g_Gs[s][KSEL][0])[i] = 0.0f;

    // compute seg/prob for 8 pixels per thread, straight from negative_logits
    int  seg[8];
    float pv[8];
    int  bin[8];
    #pragma unroll
    for (int j = 0; j < 8; j++) {
        int i = t + j * 1024;
        int b = i >> 12, rem = i & 4095;
        const float* pn = nl + (size_t)b * NCLS * HW + rem;
        float l0 = pn[0], l1 = pn[HW], l2 = pn[2 * HW], l3 = pn[3 * HW];
        int amax = 0; float m = l0;
        if (l1 > m) { m = l1; amax = 1; }
        if (l2 > m) { m = l2; amax = 2; }
        if (l3 > m) { m = l3; amax = 3; }
        float sum = __expf(l0 - m) + __expf(l1 - m) + __expf(l2 - m) + __expf(l3 - m);
        seg[j] = amax;
        pv[j]  = 1.0f / sum;
        int bb = (int)((pv[j] - 0.25f) * (1024.0f / 0.75f));
        bin[j] = max(0, min(NBIN - 1, bb));
    }

    for (int i = t; i < NBIN; i += 1024) hist[i] = 0;
    if (t == 0) s_cnt = 0;
    __syncthreads();

    #pragma unroll
    for (int j = 0; j < 8; j++)
        if (seg[j] != s) atomicAdd(&hist[bin[j]], 1);
    __syncthreads();

    if (t < 32) {
        int sum = 0;
        #pragma unroll
        for (int j = 0; j < 32; j++) sum += hist[t * 32 + j];
        s_chunk[t] = sum;
    }
    __syncthreads();
    if (t == 0) {
        int cum = 0, binThr = 0;
        for (int cb = 31; cb >= 0; cb--) {
            if (cum + s_chunk[cb] >= KSEL) {
                for (int bb = cb * 32 + 31; bb >= cb * 32; bb--) {
                    cum += hist[bb];
                    if (cum >= KSEL) { binThr = bb; break; }
                }
                break;
            }
            cum += s_chunk[cb];
        }
        s_binThr = binThr;
    }
    __syncthreads();
    int binThr = s_binThr;

    #pragma unroll
    for (int j = 0; j < 8; j++) {
        if (seg[j] != s && bin[j] >= binThr) {
            int pos = atomicAdd(&s_cnt, 1);
            if (pos < MAXCAND) { cv[pos] = pv[j]; ci[pos] = t + j * 1024; }
        }
    }
    __syncthreads();
    int M = min(s_cnt, MAXCAND);

    // exact rank (value desc, index asc tie-break == lax.top_k)
    for (int c = t; c < M; c += 1024) {
        float v = cv[c]; int id = ci[c];
        int r = 0;
        for (int m = 0; m < M; m++) {
            float vm = cv[m];
            if (vm > v || (vm == v && ci[m] < id)) r++;
        }
        if (r < KSEL) s_sel[r] = id;
    }
    __syncthreads();

    // gather + normalize + pre-scale the 50 selected negatives
    {
        int w = t >> 5, lane = t & 31;
        for (int k = w; k < KSEL; k += 32) {
            int n = s_sel[k];
            int b = n >> 12, rem = n & 4095;
            const float* p = neg + (size_t)b * CC * HW + rem;
            float v[4]; float ss = 0.f;
            #pragma unroll
            for (int j = 0; j < 4; j++) {
                int c = lane + j * 32;
                v[j] = p[(size_t)c * HW];
                ss += v[j] * v[j];
            }
            #pragma unroll
            for (int off = 16; off; off >>= 1) ss += __shfl_xor_sync(0xffffffffu, ss, off);
            float inv = SCALE / fmaxf(sqrtf(ss), 1e-12f);
            #pragma unroll
            for (int j = 0; j < 4; j++) {
                int c = lane + j * 32;
                g_Gs[s][k][c] = v[j] * inv;
            }
        }
    }
}

// ---------------- kernel 2: fused norm + class-sorted block GEMM + loss + output ----------------
// 128 blocks x 512 threads; block owns 64 consecutive pixels.
__global__ __launch_bounds__(512, 1) void k_fused(const float* __restrict__ inp,
                                                  const float* __restrict__ pos,
                                                  const float* __restrict__ il,
                                                  float* __restrict__ out) {
    extern __shared__ float sm[];
    float* sX    = sm + OFF_X;
    float* sP    = sm + OFF_P;
    float* sG    = sm + OFF_G;
    float* sRed  = sm + OFF_RED;
    float* sEx   = sm + OFF_EX;
    float* sInv  = sm + OFF_INV;
    float* sInvP = sm + OFF_INVP;
    float* sNom  = sm + OFF_NOM;
    int*   sCls  = (int*)(sm + OFF_CLS);
    int*   sPerm = (int*)(sm + OFF_PERM);
    int*   sSlot = (int*)(sm + OFF_SLOT);
    int*   sCnt  = (int*)(sm + OFF_CNT);

    int tid = threadIdx.x;
    int n   = tid & 63;
    int cg  = tid >> 6;                  // 0..7 channel group
    int px0 = blockIdx.x * 64;
    int b   = px0 >> 12, rem = px0 & 4095;

    if (tid < 8) sCnt[tid] = 0;

    // ---- Phase A: load x/p to registers, partial norms; tid<64: class from input_logits ----
    float xv[16], pv[16];
    {
        const float* bx = inp + (size_t)b * CC * HW + rem + n;
        const float* bp = pos + (size_t)b * CC * HW + rem + n;
        float sx2 = 0.f, sp2 = 0.f, sxp = 0.f;
        #pragma unroll
        for (int j = 0; j < 16; j++) {
            int c = cg * 16 + j;
            xv[j] = bx[(size_t)c * HW];
            pv[j] = bp[(size_t)c * HW];
            sx2 += xv[j] * xv[j];
            sp2 += pv[j] * pv[j];
            sxp += xv[j] * pv[j];
        }
        sRed[(0 * 8 + cg) * 64 + n] = sx2;
        sRed[(1 * 8 + cg) * 64 + n] = sp2;
        sRed[(2 * 8 + cg) * 64 + n] = sxp;
    }
    if (tid < 64) {
        const float* pi = il + (size_t)b * NCLS * HW + rem + tid;
        float l0 = pi[0], l1 = pi[HW], l2 = pi[2 * HW], l3 = pi[3 * HW];
        int amax = 0; float m = l0;
        if (l1 > m) { m = l1; amax = 1; }
        if (l2 > m) { m = l2; amax = 2; }
        if (l3 > m) { m = l3; amax = 3; }
        sCls[tid] = amax;
    }
    __syncthreads();

    // ---- Phase B: load G (all classes, KPAD rows) into smem; F: finalize norms + count ----
    {
        const float4* gsrc = (const float4*)g_Gs;     // 4*56*128/4 = 7168 float4
        #pragma unroll
        for (int it = 0; it < 14; it++) {
            int f4 = tid + it * 512;
            int cls = f4 / 1792;                      // 56*128/4 per class
            int r4  = f4 - cls * 1792;
            float4 v = gsrc[f4];
            *(float4*)&sG[cls * CS + r4 * 4] = v;
        }
    }
    if (tid < 64) {
        float sx2 = 0.f, sp2 = 0.f, sxp = 0.f;
        #pragma unroll
        for (int g = 0; g < 8; g++) {
            sx2 += sRed[(0 * 8 + g) * 64 + tid];
            sp2 += sRed[(1 * 8 + g) * 64 + tid];
            sxp += sRed[(2 * 8 + g) * 64 + tid];
        }
        float invi = 1.0f / fmaxf(sqrtf(sx2), 1e-12f);
        float invp = 1.0f / fmaxf(sqrtf(sp2), 1e-12f);
        sInv[tid]  = invi;
        sInvP[tid] = invp;
        sNom[tid]  = exp2f(sxp * invi * invp * SCALE);
        atomicAdd(&sCnt[sCls[tid]], 1);
    }
    __syncthreads();

    if (tid == 0) {
        int acc = 0;
        #pragma unroll
        for (int c = 0; c < 4; c++) { sCnt[4 + c] = acc; acc += sCnt[c]; }
    }
    __syncthreads();
    if (tid < 64) {
        int pos2 = atomicAdd(&sCnt[4 + sCls[tid]], 1);
        sPerm[pos2] = tid;       // slot -> pixel
        sSlot[tid]  = pos2;      // pixel -> slot
    }
    __syncthreads();

    // ---- Phase A3: store normalized x̂/p̂ at class-sorted (permuted) rows ----
    {
        float invi = sInv[n], invp = sInvP[n];
        int slot = sSlot[n];
        float* dx = sX + slot * RS + cg * 16;
        float* dp = sP + slot * RS + cg * 16;
        #pragma unroll
        for (int j4 = 0; j4 < 4; j4++) {
            *(float4*)&dx[j4 * 4] = make_float4(xv[j4*4]*invi, xv[j4*4+1]*invi,
                                                xv[j4*4+2]*invi, xv[j4*4+3]*invi);
            *(float4*)&dp[j4 * 4] = make_float4(pv[j4*4]*invp, pv[j4*4+1]*invp,
                                                pv[j4*4+2]*invp, pv[j4*4+3]*invp);
        }
    }
    __syncthreads();

    // ---- Phase C: register-tiled GEMM, thread = (sorted slot, 14 negatives) ----
    if (tid < 256) {
        int lane = tid & 31, warp = tid >> 5;        // warps 0..7
        int half = warp & 1, cg2 = warp >> 1;        // cg2 0..3
        int slot = half * 32 + lane;
        int pix  = sPerm[slot];
        int cls  = sCls[pix];
        const float* gx = sX + slot * RS;
        const float* gp = sP + slot * RS;
        const float* gg = sG + cls * CS + (cg2 * 14) * CC;

        u64 aN[14], aA[14];
        #pragma unroll
        for (int kk = 0; kk < 14; kk++) { aN[kk] = 0ull; aA[kk] = 0ull; }

        #pragma unroll 2
        for (int c4 = 0; c4 < 32; c4++) {
            ulonglong2 x2 = *(const ulonglong2*)&gx[c4 * 4];
            ulonglong2 p2 = *(const ulonglong2*)&gp[c4 * 4];
            #pragma unroll
            for (int kk = 0; kk < 14; kk++) {
                ulonglong2 g2 = *(const ulonglong2*)&gg[kk * CC + c4 * 4];
                fma2(aN[kk], x2.x, g2.x); fma2(aN[kk], x2.y, g2.y);
                fma2(aA[kk], p2.x, g2.x); fma2(aA[kk], p2.y, g2.y);
            }
        }

        float eN = 0.f, eA = 0.f;
        #pragma unroll
        for (int kk = 0; kk < 14; kk++) {
            if (cg2 * 14 + kk < KSEL) {
                float2 tn = upk(aN[kk]);
                float2 ta = upk(aA[kk]);
                eN += exp2f(tn.x + tn.y);
                eA += exp2f(ta.x + ta.y);
            }
        }
        sEx[cg2 * 64 + slot]       = eN;
        sEx[(4 + cg2) * 64 + slot] = eA;
    }
    __syncthreads();

    // ---- epilogue: per-pixel loss terms, block reduce, grid ticket ----
    if (tid < 64) {
        float accN = 0.f, accA = 0.f;
        #pragma unroll
        for (int g = 0; g < 4; g++) {
            accN += sEx[g * 64 + tid];
            accA += sEx[(4 + g) * 64 + tid];
        }
        float nom = sNom[sPerm[tid]];
        float term = logf(nom / (accN + nom + 1e-8f))
                   + logf(nom / (accA + nom + 1e-8f));
        #pragma unroll
        for (int off = 16; off; off >>= 1)
            term += __shfl_xor_sync(0xffffffffu, term, off);
        if ((tid & 31) == 0) atomicAdd(&g_acc, term);
    }
    __syncthreads();

    if (tid == 0) {
        __threadfence();
        unsigned int ticket = atomicAdd(&g_tick, 1u);
        if (ticket == gridDim.x - 1) {
            float v = atomicAdd(&g_acc, 0.0f);
            out[0] = -v / (float)NPIX;
        }
    }
}

// ---------------- launch ----------------
extern "C" void kernel_launch(void* const* d_in, const int* in_sizes, int n_in,
                              void* d_out, int out_size) {
    const float* inp = (const float*)d_in[0];   // input    [2,128,64,64]
    const float* pos = (const float*)d_in[1];   // positive
    const float* neg = (const float*)d_in[2];   // negative
    const float* il  = (const float*)d_in[3];   // input_logits    [2,4,64,64]
    const float* nl  = (const float*)d_in[4];   // negative_logits
    float* out = (float*)d_out;

    cudaFuncSetAttribute(k_fused, cudaFuncAttributeMaxDynamicSharedMemorySize, SMEM_BYTES);

    k_select<<<NCLS, 1024>>>(neg, nl);
    k_fused<<<NPIX / 64, 512, SMEM_BYTES>>>(inp, pos, il, out);
}